// round 17
// baseline (speedup 1.0000x reference)
#include <cuda_runtime.h>
#include <cuda_bf16.h>
#include <math.h>
#include <cstdint>

// Problem dims
#define TT 1024
#define BB 128
#define VV 512
#define HH 2048
#define OO 512

constexpr int NTH    = 256;          // helper kernels / phase 1
constexpr int NTHP3  = 512;          // phase-3 GEMM (16 warps)
constexpr int NTHS   = 1024;         // scan kernel (32 warps -> 8/SMSP)
constexpr int KSPLIT = 8;
constexpr int NTILES = HH / 128;     // 16
constexpr int KCH    = HH / KSPLIT;  // 256
constexpr int KSTAGE = 32;           // fp32 K-depth per stage

constexpr int    BH  = BB * HH;
constexpr size_t TBH = (size_t)TT * BH;
constexpr size_t TBO = (size_t)TT * BB * OO;
constexpr size_t PART_STRIDE = (size_t)KSPLIT * BH;   // one parity buffer

// Padded SMEM tile geometry: 128 rows x 16 data words (32 bf16) + 4 pad
constexpr int TW     = 20;                  // words per row
constexpr int TILE_W = 128 * TW;            // 2560 words per tile
constexpr int TILE_B = TILE_W * 4;          // 10240 bytes per tile

constexpr int SMEM_SCAN = 20 * TILE_B;      // 204800 B
constexpr int SMEM_P3   = 8 * TILE_B;       // 81920 B

// -------- device scratch --------
__device__ float g_P[VV * HH];
__device__ float g_hall[TBH];
__device__ float g_part[2 * PART_STRIDE];   // parity double-buffered partials
__device__ int   g_ctr_tile[TT][NTILES];    // split-K partial arrivals
__device__ int   g_ready[TT][NTILES];       // h-tile-ready counts
// h pre-split (bf16x2 packed hi/lo), parity-buffered
__device__ uint32_t g_hs_hi[2][BB][HH / 2];
__device__ uint32_t g_hs_lo[2][BB][HH / 2];
// Pre-split weights, tiled [slice][stage*2+hl][row(128)][word(16)]
__device__ uint4 g_whsplit4[(size_t)128 * 16 * 512];   // 16 MB
__device__ uint4 g_wosplit4[(size_t)4 * 128 * 512];    //  4 MB

// ============================================================================
// sync + math helpers
// ============================================================================
__device__ __forceinline__ int ld_acquire(const int* p) {
    int v;
    asm volatile("ld.global.acquire.gpu.b32 %0, [%1];" : "=r"(v) : "l"(p) : "memory");
    return v;
}
__device__ __forceinline__ void red_release(int* p) {
    asm volatile("red.global.release.gpu.add.s32 [%0], 1;" :: "l"(p) : "memory");
}
__device__ __forceinline__ void spin_acq(const int* p, int v) {
    while (ld_acquire(p) < v) { }
}
__device__ __forceinline__ float fast_tanh(float x) {
    float e;
    asm("ex2.approx.f32 %0, %1;" : "=f"(e) : "f"(x * 2.8853900817779268f));
    float r;
    asm("rcp.approx.f32 %0, %1;" : "=f"(r) : "f"(e + 1.0f));
    return fmaf(-2.0f, r, 1.0f);
}

__device__ __forceinline__ void split2(float v0, float v1,
                                       uint32_t& whi, uint32_t& wlo) {
    __nv_bfloat16 h0 = __float2bfloat16_rn(v0);
    __nv_bfloat16 h1 = __float2bfloat16_rn(v1);
    __nv_bfloat16 l0 = __float2bfloat16_rn(v0 - __bfloat162float(h0));
    __nv_bfloat16 l1 = __float2bfloat16_rn(v1 - __bfloat162float(h1));
    whi = ((uint32_t)__bfloat16_as_ushort(h1) << 16) | __bfloat16_as_ushort(h0);
    wlo = ((uint32_t)__bfloat16_as_ushort(l1) << 16) | __bfloat16_as_ushort(l0);
}

__device__ __forceinline__ void mma_bf16(float* d, const uint32_t* a,
                                         const uint32_t* b) {
    asm volatile(
        "mma.sync.aligned.m16n8k16.row.col.f32.bf16.bf16.f32 "
        "{%0,%1,%2,%3}, {%4,%5,%6,%7}, {%8,%9}, {%0,%1,%2,%3};"
        : "+f"(d[0]), "+f"(d[1]), "+f"(d[2]), "+f"(d[3])
        : "r"(a[0]), "r"(a[1]), "r"(a[2]), "r"(a[3]), "r"(b[0]), "r"(b[1]));
}

__device__ __forceinline__ void ldsm4(uint32_t* r, uint32_t addr) {
    asm volatile("ldmatrix.sync.aligned.m8n8.x4.shared.b16 {%0,%1,%2,%3}, [%4];"
                 : "=r"(r[0]), "=r"(r[1]), "=r"(r[2]), "=r"(r[3]) : "r"(addr));
}

__device__ __forceinline__ uint32_t smem_u32(const void* p) {
    return (uint32_t)__cvta_generic_to_shared(p);
}

// ============================================================================
// Scan MMA stage, warp tile 16 (M) x 32 (N), K=32, 3-product bf16x2.
// Per-output accumulation order (stage asc, kk 0->1, hh,hl,lh) identical.
// ============================================================================
__device__ __forceinline__ void mma_stage_m16n32(
    uint32_t a_hi, uint32_t a_lo, uint32_t b_hi, uint32_t b_lo,
    int wrow, int wcol, int lane, float (&d)[4][4])
{
    const int arow = (lane & 7) + ((lane >> 3) & 1) * 8;
    const int acol = ((lane >> 4) & 1) * 4;
    const int brow = (lane & 7) + ((lane >> 4) & 1) * 8;
    const int bcol = ((lane >> 3) & 1) * 4;
    #pragma unroll
    for (int kk = 0; kk < 2; ++kk) {
        uint32_t ah[4], al[4];
        uint32_t bh[2][4], bl[2][4];
        {
            const uint32_t off =
                (uint32_t)(((wrow + arow) * TW + kk * 8 + acol) * 4);
            ldsm4(ah, a_hi + off);
            ldsm4(al, a_lo + off);
        }
        #pragma unroll
        for (int np = 0; np < 2; ++np) {
            const uint32_t off =
                (uint32_t)(((wcol + np * 16 + brow) * TW + kk * 8 + bcol) * 4);
            ldsm4(bh[np], b_hi + off);
            ldsm4(bl[np], b_lo + off);
        }
        #pragma unroll
        for (int np = 0; np < 2; ++np)
            #pragma unroll
            for (int h = 0; h < 2; ++h)
                mma_bf16(d[2 * np + h], ah, &bh[np][2 * h]);   // hi*hi
        #pragma unroll
        for (int np = 0; np < 2; ++np)
            #pragma unroll
            for (int h = 0; h < 2; ++h)
                mma_bf16(d[2 * np + h], ah, &bl[np][2 * h]);   // hi*lo
        #pragma unroll
        for (int np = 0; np < 2; ++np)
            #pragma unroll
            for (int h = 0; h < 2; ++h)
                mma_bf16(d[2 * np + h], al, &bh[np][2 * h]);   // lo*hi
    }
}

// Phase-3 MMA stage, warp tile 16 (M) x 64 (N) (the proven R16 scan tile)
__device__ __forceinline__ void mma_stage_m16(
    uint32_t a_hi, uint32_t a_lo, uint32_t b_hi, uint32_t b_lo,
    int wrow, int wcol, int lane, float (&d)[8][4])
{
    const int arow = (lane & 7) + ((lane >> 3) & 1) * 8;
    const int acol = ((lane >> 4) & 1) * 4;
    const int brow = (lane & 7) + ((lane >> 4) & 1) * 8;
    const int bcol = ((lane >> 3) & 1) * 4;
    #pragma unroll
    for (int kk = 0; kk < 2; ++kk) {
        uint32_t ah[4], al[4];
        uint32_t bh[4][4], bl[4][4];
        {
            const uint32_t off =
                (uint32_t)(((wrow + arow) * TW + kk * 8 + acol) * 4);
            ldsm4(ah, a_hi + off);
            ldsm4(al, a_lo + off);
        }
        #pragma unroll
        for (int np = 0; np < 4; ++np) {
            const uint32_t off =
                (uint32_t)(((wcol + np * 16 + brow) * TW + kk * 8 + bcol) * 4);
            ldsm4(bh[np], b_hi + off);
            ldsm4(bl[np], b_lo + off);
        }
        #pragma unroll
        for (int np = 0; np < 4; ++np)
            #pragma unroll
            for (int h = 0; h < 2; ++h)
                mma_bf16(d[2 * np + h], ah, &bh[np][2 * h]);   // hi*hi
        #pragma unroll
        for (int np = 0; np < 4; ++np)
            #pragma unroll
            for (int h = 0; h < 2; ++h)
                mma_bf16(d[2 * np + h], ah, &bl[np][2 * h]);   // hi*lo
        #pragma unroll
        for (int np = 0; np < 4; ++np)
            #pragma unroll
            for (int h = 0; h < 2; ++h)
                mma_bf16(d[2 * np + h], al, &bh[np][2 * h]);   // lo*hi
    }
}

// ---- scan A feed (1024 thr): thread covers row tid>>3, 2 words at (tid&7)*2 ----
struct ASplit { uint2 h, l; };

__device__ __forceinline__ void a_ldg_s(ASplit& g, int par, int prow, int kw)
{
    g.h = *(const uint2*)&g_hs_hi[par][prow][kw];
    g.l = *(const uint2*)&g_hs_lo[par][prow][kw];
}
__device__ __forceinline__ void a_sts_s(uint32_t* sm, int buf, const ASplit& g,
                                        int prow, int pq)
{
    uint32_t* hi = sm + (buf * 2 + 0) * TILE_W + prow * TW + pq;
    uint32_t* lo = sm + (buf * 2 + 1) * TILE_W + prow * TW + pq;
    *(uint2*)hi = g.h;
    *(uint2*)lo = g.l;
}

// ============================================================================
// Weight pre-split kernels (run once per launch; tiny)
// ============================================================================
__global__ void presplit_wh(const float* __restrict__ Wh)
{
    const int idx = blockIdx.x * blockDim.x + threadIdx.x;  // < 128*8*128*16
    const int w     = idx & 15;
    const int row   = (idx >> 4) & 127;
    const int s     = (idx >> 11) & 7;
    const int slice = idx >> 14;          // j*8 + z
    const int j = slice >> 3, z = slice & 7;
    const int n = j * 128 + row;
    const int k = z * 256 + s * 32 + w * 2;
    uint32_t whi, wlo;
    split2(Wh[(size_t)n * HH + k], Wh[(size_t)n * HH + k + 1], whi, wlo);
    uint32_t* dst = (uint32_t*)g_whsplit4;
    const size_t tb = (((size_t)slice * 16 + s * 2) * 128 + row) * 16 + w;
    dst[tb] = whi;
    dst[tb + 128 * 16] = wlo;   // lo tile follows hi tile
}

__global__ void presplit_wo(const float* __restrict__ Wo)
{
    const int idx = blockIdx.x * blockDim.x + threadIdx.x;  // < 4*64*128*16
    const int w   = idx & 15;
    const int row = (idx >> 4) & 127;
    const int s   = (idx >> 11) & 63;
    const int nj  = idx >> 17;
    const int n = nj * 128 + row;
    const int k = s * 32 + w * 2;
    uint32_t whi, wlo;
    split2(Wo[(size_t)n * HH + k], Wo[(size_t)n * HH + k + 1], whi, wlo);
    uint32_t* dst = (uint32_t*)g_wosplit4;
    const size_t tb = (((size_t)nj * 128 + s * 2) * 128 + row) * 16 + w;
    dst[tb] = whi;
    dst[tb + 128 * 16] = wlo;
}

// ============================================================================
// Persistent scan kernel: 1024 threads (32 warps, 8/SMSP).
// Warp tile 16x32; feed = pure copy of pre-split h; dataflow sync with
// single-thread release/acquire; parity-buffered partials.
// grid (16 N-tiles, 8 K-splits) = 128 CTAs, occ 1.
// ============================================================================
__global__ void __launch_bounds__(NTHS, 1)
scan_mma(const int* __restrict__ x,
         const float* __restrict__ bh)
{
    extern __shared__ uint32_t sm[];
    const uint32_t smaddr = smem_u32(sm);

    const int tid  = threadIdx.x;
    const int wid  = tid >> 5;
    const int lane = tid & 31;
    const int j    = blockIdx.x;
    const int z    = blockIdx.y;
    const int nbase = j * 128;
    const int p0    = 2 * z;
    const int p1    = 2 * z + 1;

    // 32 warps: 8 M-blocks of 16 rows x 4 N-blocks of 32 cols
    const int wrow = (wid & 7) * 16;
    const int wcol = (wid >> 3) * 32;
    // A feed: row tid>>3, 2 words at (tid&7)*2
    const int prow = tid >> 3;
    const int pq   = (tid & 7) * 2;
    const int kwb  = z * (KCH / 2) + pq;

    // reduce slice: 128 rows x 16 cols -> 2 cols per thread
    const int rrow  = tid >> 3;
    const int cq    = nbase + z * 16 + (tid & 7) * 2;
    const int wb    = cq >> 1;             // split word index

    const float2 bh2 = *(const float2*)(bh + cq);

    // ---- load this CTA's Wh slice (pre-split) into stationary SMEM tiles ----
    {
        const uint4* wsrc = g_whsplit4 + (size_t)(j * 8 + z) * 16 * 512;
        for (int r = tid; r < 16 * 128; r += NTHS) {
            const int tile = r >> 7;
            const int row  = r & 127;
            uint32_t* dst = sm + (4 + tile) * TILE_W + row * TW;
            const uint4* s4 = wsrc + (size_t)r * 4;
            #pragma unroll
            for (int q = 0; q < 4; ++q)
                *(uint4*)(dst + 4 * q) = s4[q];
        }
    }

    // ---- t = 0: h_0 = tanh(P[x_0] + bh); write fp32 + split (parity 0) ----
    {
        float2 pp = *(const float2*)(g_P + (size_t)x[rrow] * HH + cq);
        float2 v = make_float2(fast_tanh(pp.x + bh2.x), fast_tanh(pp.y + bh2.y));
        *(float2*)(g_hall + (size_t)rrow * HH + cq) = v;
        uint32_t h0, l0;
        split2(v.x, v.y, h0, l0);
        g_hs_hi[0][rrow][wb] = h0;
        g_hs_lo[0][rrow][wb] = l0;
        __syncthreads();
        if (tid == 0) red_release(&g_ready[0][j]);
    }

    for (int t = 1; t < TT; ++t) {
        const int parc = (t - 1) & 1;   // consume h_{t-1} split
        const int parw = t & 1;         // produce h_t split + partials

        // ---- dataflow waits (acquire spins, separate warps) ----
        if      (tid == 0)  spin_acq(&g_ready[t - 1][p0], KSPLIT);
        else if (tid == 32) spin_acq(&g_ready[t - 1][p1], KSPLIT);
        else if (tid == 64 && t >= 2) spin_acq(&g_ready[t - 2][j], KSPLIT);
        __syncthreads();

        float* part = g_part + (size_t)parw * PART_STRIDE + (size_t)z * BH;
        const float* pplane = g_part + (size_t)parw * PART_STRIDE;

        // prefetch reduce-phase P gather (barrier-independent)
        const float2 pf = *(const float2*)(
            g_P + (size_t)x[(size_t)t * BB + rrow] * HH + cq);

        float d[4][4];
        #pragma unroll
        for (int n = 0; n < 4; ++n)
            #pragma unroll
            for (int q = 0; q < 4; ++q) d[n][q] = 0.0f;

        ASplit g;
        a_ldg_s(g, parc, prow, kwb);
        a_sts_s(sm, 0, g, prow, pq);
        __syncthreads();

        constexpr int NS = KCH / KSTAGE;   // 8 stages
        #pragma unroll 1
        for (int s = 0; s < NS; ++s) {
            const int cur = s & 1;
            if (s + 1 < NS) a_ldg_s(g, parc, prow, kwb + (s + 1) * 16);
            mma_stage_m16n32(smaddr + (cur * 2 + 0) * TILE_B,
                             smaddr + (cur * 2 + 1) * TILE_B,
                             smaddr + (4 + s * 2 + 0) * TILE_B,
                             smaddr + (4 + s * 2 + 1) * TILE_B,
                             wrow, wcol, lane, d);
            if (s + 1 < NS) a_sts_s(sm, cur ^ 1, g, prow, pq);
            __syncthreads();
        }

        // store split-K partial plane (parity buffer; WAR-safe via t-2 wait)
        #pragma unroll
        for (int n = 0; n < 4; ++n) {
            const int r0 = wrow + (lane >> 2);
            const int c0 = nbase + wcol + n * 8 + (lane & 3) * 2;
            *(float2*)(part + (size_t)r0 * HH + c0) =
                make_float2(d[n][0], d[n][1]);
            *(float2*)(part + (size_t)(r0 + 8) * HH + c0) =
                make_float2(d[n][2], d[n][3]);
        }
        __syncthreads();

        // tile barrier: bar orders all CTA stores before tid0's release-red
        if (tid == 0) {
            red_release(&g_ctr_tile[t][j]);
            spin_acq(&g_ctr_tile[t][j], KSPLIT);
        }
        __syncthreads();

        // distributed reduce + tanh; write fp32 h AND its bf16 hi/lo split
        {
            float2 v = make_float2(pf.x + bh2.x, pf.y + bh2.y);
            const size_t off = (size_t)rrow * HH + cq;
            #pragma unroll
            for (int z2 = 0; z2 < KSPLIT; ++z2) {
                float2 u = __ldcg((const float2*)(pplane + (size_t)z2 * BH + off));
                v.x += u.x; v.y += u.y;
            }
            v = make_float2(fast_tanh(v.x), fast_tanh(v.y));
            *(float2*)(g_hall + (size_t)t * BH + off) = v;
            uint32_t h0, l0;
            split2(v.x, v.y, h0, l0);
            g_hs_hi[parw][rrow][wb] = h0;
            g_hs_lo[parw][rrow][wb] = l0;
        }
        __syncthreads();

        // signal: this CTA's slice of h-tile j at step t is visible
        if (tid == 0) red_release(&g_ready[t][j]);
    }
}

// ============================================================================
// Phase-3 GEMM: out = h_all @ Wo^T + bo.  512 threads, warp tile 16x64
// (the proven R16 scan layout).  grid (4 N-tiles, 1024 M-tiles), 64 stages.
// ============================================================================
__global__ void __launch_bounds__(NTHP3, 1)
gemm_out_mma(const float* __restrict__ bo,
             float* __restrict__ out)
{
    extern __shared__ uint32_t sm[];
    const uint32_t smaddr = smem_u32(sm);

    const int tid  = threadIdx.x;
    const int wid  = tid >> 5;
    const int lane = tid & 31;
    const int nj   = blockIdx.x;
    const int nbase = nj * 128;
    const size_t mbase = (size_t)blockIdx.y * 128;

    // 16 warps: 8 M-blocks of 16 x 2 N-blocks of 64
    const int wrow = (wid & 7) * 16;
    const int wcol = (wid >> 3) * 64;
    // A producer: row tid>>2, 8 floats at (tid&3)*8 -> 4 words at pq
    const int prow = tid >> 2;
    const int pcol = (tid & 3) * 8;
    const int pq   = (tid & 3) * 4;
    const int q0   = tid & 3;

    const float* Asrc = g_hall + mbase * HH;
    const uint4* bsrc = g_wosplit4 + (size_t)nj * 128 * 512;

    float d[8][4];
    #pragma unroll
    for (int n = 0; n < 8; ++n)
        #pragma unroll
        for (int q = 0; q < 4; ++q) d[n][q] = 0.0f;

    float4 ra[2];
    uint4  bw[2];
    auto a_ldg3 = [&](int s) {
        const float* ap = Asrc + (size_t)prow * HH + pcol + s * KSTAGE;
        ra[0] = *(const float4*)(ap);
        ra[1] = *(const float4*)(ap + 4);
    };
    auto b_ldg3 = [&](int s) {
        const uint4* p = bsrc + (size_t)(s * 2) * 512 + (size_t)prow * 4 + q0;
        bw[0] = p[0];       // hi
        bw[1] = p[512];     // lo
    };
    auto a_sts3 = [&](int buf) {
        uint32_t* hi = sm + (buf * 2 + 0) * TILE_W + prow * TW + pq;
        uint32_t* lo = sm + (buf * 2 + 1) * TILE_W + prow * TW + pq;
        uint32_t h0, l0, h1, l1, h2, l2, h3, l3;
        split2(ra[0].x, ra[0].y, h0, l0);
        split2(ra[0].z, ra[0].w, h1, l1);
        split2(ra[1].x, ra[1].y, h2, l2);
        split2(ra[1].z, ra[1].w, h3, l3);
        *(uint4*)hi = make_uint4(h0, h1, h2, h3);
        *(uint4*)lo = make_uint4(l0, l1, l2, l3);
    };
    auto b_sts3 = [&](int buf) {
        uint32_t* hi = sm + (4 + buf * 2 + 0) * TILE_W + prow * TW + q0 * 4;
        uint32_t* lo = sm + (4 + buf * 2 + 1) * TILE_W + prow * TW + q0 * 4;
        *(uint4*)hi = bw[0];
        *(uint4*)lo = bw[1];
    };

    a_ldg3(0);
    b_ldg3(0);
    a_sts3(0);
    b_sts3(0);
    __syncthreads();

    constexpr int NS = HH / KSTAGE;   // 64 stages
    #pragma unroll 1
    for (int s = 0; s < NS; ++s) {
        const int cur = s & 1;
        if (s + 1 < NS) { a_ldg3(s + 1); b_ldg3(s + 1); }
        mma_stage_m16(smaddr + (cur * 2 + 0) * TILE_B,
                      smaddr + (cur * 2 + 1) * TILE_B,
                      smaddr + (4 + cur * 2 + 0) * TILE_B,
                      smaddr + (4 + cur * 2 + 1) * TILE_B,
                      wrow, wcol, lane, d);
        if (s + 1 < NS) { a_sts3(cur ^ 1); b_sts3(cur ^ 1); }
        __syncthreads();
    }

    // epilogue: + bias, store
    #pragma unroll
    for (int n = 0; n < 8; ++n) {
        const int r0 = wrow + (lane >> 2);
        const int c0 = nbase + wcol + n * 8 + (lane & 3) * 2;
        const float2 bv = *(const float2*)(bo + c0);
        *(float2*)(out + (mbase + r0) * OO + c0) =
            make_float2(d[n][0] + bv.x, d[n][1] + bv.y);
        *(float2*)(out + (mbase + r0 + 8) * OO + c0) =
            make_float2(d[n][2] + bv.x, d[n][3] + bv.y);
    }
}

// ============================================================================
// Phase-1 fp32 FFMA2 GEMM (exact; verified R6 code)
// ============================================================================
typedef unsigned long long ull;
__device__ __forceinline__ void ffma2(ull& d, ull a, ull b) {
    asm("fma.rn.f32x2 %0, %1, %2, %3;" : "=l"(d) : "l"(a), "l"(b), "l"(d));
}
__device__ __forceinline__ void unpack2(float& lo, float& hi, ull v) {
    asm("mov.b64 {%0,%1}, %2;" : "=f"(lo), "=f"(hi) : "l"(v));
}
__device__ __forceinline__ ull dup2(float v) {
    ull r; asm("mov.b64 %0, {%1,%1};" : "=l"(r) : "f"(v)); return r;
}
constexpr int KB = 16;
struct SmemT {
    float As[2][KB][132];
    float Bs[2][KB][140];
};
__device__ __forceinline__ int skew(int n) { return n + ((n >> 5) << 2); }

__device__ __forceinline__ void gemm_tile(SmemT& s,
    const float* __restrict__ Ag, int lda,
    const float* __restrict__ Bg, int ldb,
    int nk, ull (&acc)[4][8])
{
    const int tid = threadIdx.x;
    const int am  = tid >> 2;
    const int ak  = (tid & 3) * 4;
    const int tm  = (tid >> 4) * 8;
    const int tn  = (tid & 15) * 8;
    const int ptn = skew(tn);
    const int pb0 = skew(am);
    const int pb1 = skew(am + 64);

    const float* Arow0 = Ag + (size_t)am        * lda + ak;
    const float* Arow1 = Ag + (size_t)(am + 64) * lda + ak;
    const float* Brow0 = Bg + (size_t)am        * ldb + ak;
    const float* Brow1 = Bg + (size_t)(am + 64) * ldb + ak;

    float4 ra0, ra1, rb0, rb1;
    auto ldg = [&](int kt) {
        const int kk = kt * KB;
        ra0 = *(const float4*)(Arow0 + kk);
        ra1 = *(const float4*)(Arow1 + kk);
        rb0 = *(const float4*)(Brow0 + kk);
        rb1 = *(const float4*)(Brow1 + kk);
    };
    auto sts = [&](int buf) {
        s.As[buf][ak + 0][am]      = ra0.x; s.As[buf][ak + 1][am]      = ra0.y;
        s.As[buf][ak + 2][am]      = ra0.z; s.As[buf][ak + 3][am]      = ra0.w;
        s.As[buf][ak + 0][am + 64] = ra1.x; s.As[buf][ak + 1][am + 64] = ra1.y;
        s.As[buf][ak + 2][am + 64] = ra1.z; s.As[buf][ak + 3][am + 64] = ra1.w;
        s.Bs[buf][ak + 0][pb0] = rb0.x; s.Bs[buf][ak + 1][pb0] = rb0.y;
        s.Bs[buf][ak + 2][pb0] = rb0.z; s.Bs[buf][ak + 3][pb0] = rb0.w;
        s.Bs[buf][ak + 0][pb1] = rb1.x; s.Bs[buf][ak + 1][pb1] = rb1.y;
        s.Bs[buf][ak + 2][pb1] = rb1.z; s.Bs[buf][ak + 3][pb1] = rb1.w;
    };

    ldg(0); sts(0);
    __syncthreads();
    for (int kt = 0; kt < nk; ++kt) {
        const int cur = kt & 1;
        if (kt + 1 < nk) ldg(kt + 1);
        #pragma unroll
        for (int k = 0; k < KB; ++k) {
            ulonglong2 a01 = *(const ulonglong2*)&s.As[cur][k][tm];
            ulonglong2 a23 = *(const ulonglong2*)&s.As[cur][k][tm + 4];
            float4 b0 = *(const float4*)&s.Bs[cur][k][ptn];
            float4 b1 = *(const float4*)&s.Bs[cur][k][ptn + 4];
            ull d0 = dup2(b0.x), d1 = dup2(b0.y), d2 = dup2(b0.z), d3 = dup2(b0.w);
            ull d4 = dup2(b1.x), d5 = dup2(b1.y), d6 = dup2(b1.z), d7 = dup2(b1.w);
            ffma2(acc[0][0], a01.x, d0); ffma2(acc[0][1], a01.x, d1);
            ffma2(acc[0][2], a01.x, d2); ffma2(acc[0][3], a01.x, d3);
            ffma2(acc[0][4], a01.x, d4); ffma2(acc[0][5], a01.x, d5);
            ffma2(acc[0][6], a01.x, d6); ffma2(acc[0][7], a01.x, d7);
            ffma2(acc[1][0], a01.y, d0); ffma2(acc[1][1], a01.y, d1);
            ffma2(acc[1][2], a01.y, d2); ffma2(acc[1][3], a01.y, d3);
            ffma2(acc[1][4], a01.y, d4); ffma2(acc[1][5], a01.y, d5);
            ffma2(acc[1][6], a01.y, d6); ffma2(acc[1][7], a01.y, d7);
            ffma2(acc[2][0], a23.x, d0); ffma2(acc[2][1], a23.x, d1);
            ffma2(acc[2][2], a23.x, d2); ffma2(acc[2][3], a23.x, d3);
            ffma2(acc[2][4], a23.x, d4); ffma2(acc[2][5], a23.x, d5);
            ffma2(acc[2][6], a23.x, d6); ffma2(acc[2][7], a23.x, d7);
            ffma2(acc[3][0], a23.y, d0); ffma2(acc[3][1], a23.y, d1);
            ffma2(acc[3][2], a23.y, d2); ffma2(acc[3][3], a23.y, d3);
            ffma2(acc[3][4], a23.y, d4); ffma2(acc[3][5], a23.y, d5);
            ffma2(acc[3][6], a23.y, d6); ffma2(acc[3][7], a23.y, d7);
        }
        if (kt + 1 < nk) sts(cur ^ 1);
        __syncthreads();
    }
}

__global__ void __launch_bounds__(NTH, 1)
gemm128(const float* __restrict__ A, int lda,
        const float* __restrict__ B, int ldb,
        float* __restrict__ C, int ldc,
        const float* __restrict__ bias, int K)
{
    __shared__ SmemT s;
    const int tid   = threadIdx.x;
    const int nbase = blockIdx.x * 128;
    const int mbase = blockIdx.y * 128;

    ull acc[4][8];
    #pragma unroll
    for (int p = 0; p < 4; ++p)
        #pragma unroll
        for (int n = 0; n < 8; ++n) acc[p][n] = 0ull;

    gemm_tile(s, A + (size_t)mbase * lda, lda, B + (size_t)nbase * ldb, ldb, K / KB, acc);

    const int tm = (tid >> 4) * 8;
    const int tn = (tid & 15) * 8;
    float bv[8];
    #pragma unroll
    for (int n = 0; n < 8; ++n) bv[n] = bias[nbase + tn + n];

    #pragma unroll
    for (int p = 0; p < 4; ++p) {
        float lo[8], hi[8];
        #pragma unroll
        for (int n = 0; n < 8; ++n) {
            unpack2(lo[n], hi[n], acc[p][n]);
            lo[n] += bv[n]; hi[n] += bv[n];
        }
        const int r0 = mbase + tm + 2 * p;
        float* c0 = C + (size_t)r0 * ldc + nbase + tn;
        float* c1 = c0 + ldc;
        *(float4*)(c0)     = make_float4(lo[0], lo[1], lo[2], lo[3]);
        *(float4*)(c0 + 4) = make_float4(lo[4], lo[5], lo[6], lo[7]);
        *(float4*)(c1)     = make_float4(hi[0], hi[1], hi[2], hi[3]);
        *(float4*)(c1 + 4) = make_float4(hi[4], hi[5], hi[6], hi[7]);
    }
}

__global__ void reset_ctr_kernel()
{
    const int i = blockIdx.x * blockDim.x + threadIdx.x;
    if (i < TT * NTILES) {
        ((int*)g_ctr_tile)[i] = 0;
        ((int*)g_ready)[i] = 0;
    }
}

__global__ void copy_h_kernel(float* __restrict__ dst)
{
    const int idx = blockIdx.x * blockDim.x + threadIdx.x;
    dst[idx] = g_hall[(size_t)(TT - 1) * BH + idx];
}

extern "C" void kernel_launch(void* const* d_in, const int* in_sizes, int n_in,
                              void* d_out, int out_size)
{
    (void)in_sizes; (void)n_in;
    const int*   x   = (const int*)  d_in[0];
    const float* emb = (const float*)d_in[1];
    const float* Wi  = (const float*)d_in[2];
    const float* bi  = (const float*)d_in[3];
    const float* Wh  = (const float*)d_in[4];
    const float* bh  = (const float*)d_in[5];
    const float* Wo  = (const float*)d_in[6];
    const float* bo  = (const float*)d_in[7];
    float* out = (float*)d_out;

    float* g_P_ptr = nullptr;
    cudaGetSymbolAddress((void**)&g_P_ptr, g_P);

    cudaFuncSetAttribute(scan_mma,     cudaFuncAttributeMaxDynamicSharedMemorySize, SMEM_SCAN);
    cudaFuncSetAttribute(gemm_out_mma, cudaFuncAttributeMaxDynamicSharedMemorySize, SMEM_P3);

    // Pre-split weights into bf16 hi/lo tiled layout (one-time per launch)
    presplit_wh<<<(128 * 8 * 128 * 16) / NTH, NTH>>>(Wh);
    presplit_wo<<<(4 * 64 * 128 * 16) / NTH, NTH>>>(Wo);

    // Phase 1: P = emb @ Wi^T + bi   [512 x 2048], K=512 (exact fp32)
    gemm128<<<dim3(HH / 128, VV / 128), NTH>>>(emb, VV, Wi, VV, g_P_ptr, HH, bi, VV);

    // Phase 2: persistent mma.sync scan, 1024 threads (8 warps/SMSP)
    scan_mma<<<dim3(NTILES, KSPLIT), NTHS, SMEM_SCAN>>>(x, bh);

    // Reset flags/counters for the next replay
    reset_ctr_kernel<<<(TT * NTILES + NTH - 1) / NTH, NTH>>>();

    // Phase 3: out = h_all @ Wo^T + bo   [131072 x 512], K=2048 (512 thr)
    gemm_out_mma<<<dim3(OO / 128, (TT * BB) / 128), NTHP3, SMEM_P3>>>(bo, out);

    // Second output: final hidden state h_{T-1}  [B, H]
    if ((long long)out_size >= (long long)(TBO + (size_t)BH))
        copy_h_kernel<<<BH / NTH, NTH>>>(out + TBO);
}